// round 5
// baseline (speedup 1.0000x reference)
#include <cuda_runtime.h>

#define HW    16384
#define HW2   8192
#define Bn    8
#define Cn    10
#define NTH   128
#define NBL   512          // NBL*NTH threads, 2 px each = 131072 px

// Persistent scratch (allocation-free)
__device__ double   g_s1[40*64];   // BN1 slot partials: rows 0..19 sum, 20..39 sumsq
__device__ double   g_s2[20*64];   // BN2 slot partials
__device__ unsigned g_bar[3];      // monotonic barrier counters (never reset)

__device__ __forceinline__ float sigm(float x){ return 1.f/(1.f+__expf(-x)); }
__device__ __forceinline__ float ftanh(float x){ return fmaf(2.f, 1.f/(1.f+__expf(-2.f*x)), -1.f); }

// Monotonic ticket barrier. wait=false: arrive-only (no spin).
__device__ __forceinline__ void grid_barrier(unsigned* ctr, int tid, bool wait){
    __syncthreads();
    if (tid == 0){
        __threadfence();
        unsigned ticket = atomicAdd(ctr, 1u);
        if (wait){
            unsigned target = (ticket / NBL + 1u) * NBL;
            while ((int)(*(volatile unsigned*)ctr - target) < 0) __nanosleep(64);
            __threadfence();
        }
    }
    __syncthreads();
}

__global__ void __launch_bounds__(NTH, 4) k_fused(
    const float* __restrict__ f0, const float* __restrict__ f1,
    const float* __restrict__ h0, const float* __restrict__ h1, const float* __restrict__ h2,
    const float* __restrict__ W_att, const float* __restrict__ b_att,
    const float* __restrict__ W_r1,  const float* __restrict__ g_r1, const float* __restrict__ be_r1,
    const float* __restrict__ W_r2,  const float* __restrict__ g_r2, const float* __restrict__ be_r2,
    const float* __restrict__ Wg0, const float* __restrict__ bg0, const float* __restrict__ Wc0,
    const float* __restrict__ Wg1, const float* __restrict__ bg1, const float* __restrict__ Wc1,
    float* __restrict__ node0, float* __restrict__ node1, float* __restrict__ attOut)
{
    __shared__ float sWg0[40], sWc0[200], sWatt[20], sWr1[400];
    __shared__ float sWr2[200], sWg1[40], sWc1[200];
    __shared__ float sGB1[40], sGB2[20];     // gamma/beta
    __shared__ float sb[5];                  // b_att, bg0[0..1], bg1[0..1]
    __shared__ float sAcc1[40], sAcc2[20];
    __shared__ double sStat[40];
    __shared__ float sP1[40], sP2[20];

    int tid = threadIdx.x;
    for (int i=tid;i<40;i+=NTH)  sWg0[i]=Wg0[i];
    for (int i=tid;i<200;i+=NTH) sWc0[i]=Wc0[i];
    for (int i=tid;i<20;i+=NTH)  sWatt[i]=W_att[i];
    for (int i=tid;i<400;i+=NTH) sWr1[i]=W_r1[i];
    for (int i=tid;i<200;i+=NTH) sWr2[i]=W_r2[i];
    for (int i=tid;i<40;i+=NTH)  sWg1[i]=Wg1[i];
    for (int i=tid;i<200;i+=NTH) sWc1[i]=Wc1[i];
    if (tid<20){ sGB1[tid]=g_r1[tid]; sGB1[20+tid]=be_r1[tid]; }
    if (tid<10){ sGB2[tid]=g_r2[tid]; sGB2[10+tid]=be_r2[tid]; }
    if (tid==0){ sb[0]=b_att[0]; sb[1]=bg0[0]; sb[2]=bg0[1]; sb[3]=bg1[0]; sb[4]=bg1[1]; }
    if (tid<40) sAcc1[tid]=0.f;
    if (tid<20) sAcc2[tid]=0.f;
    __syncthreads();

    int idx = blockIdx.x*NTH + tid;      // float2 index
    int b = idx >> 13, p = idx & (HW2-1);
    long base = (long)b*Cn*HW2 + p;
    int lane = tid & 31;

    const float2* F0 = (const float2*)f0;
    const float2* F1 = (const float2*)f1;
    const float2* H0 = (const float2*)h0;
    const float2* H1 = (const float2*)h1;
    const float2* H2 = (const float2*)h2;

    // ================= Phase A =================
    // node0 = ConvGRU(x=h0, h=f0)
    {
        float2 xv[Cn], hv[Cn];
        #pragma unroll
        for (int c=0;c<Cn;c++){ xv[c]=H0[base+c*HW2]; hv[c]=F0[base+c*HW2]; }
        float g0x=sb[1], g0y=sb[1], g1x=sb[2], g1y=sb[2];
        #pragma unroll
        for (int c=0;c<Cn;c++){
            g0x = fmaf(sWg0[c],    xv[c].x, fmaf(sWg0[10+c], hv[c].x, g0x));
            g0y = fmaf(sWg0[c],    xv[c].y, fmaf(sWg0[10+c], hv[c].y, g0y));
            g1x = fmaf(sWg0[20+c], xv[c].x, fmaf(sWg0[30+c], hv[c].x, g1x));
            g1y = fmaf(sWg0[20+c], xv[c].y, fmaf(sWg0[30+c], hv[c].y, g1y));
        }
        float rx=sigm(g0x), ry=sigm(g0y), ux=sigm(g1x), uy=sigm(g1y);
        float2 rh[Cn];
        #pragma unroll
        for (int c=0;c<Cn;c++){ rh[c].x = rx*hv[c].x; rh[c].y = ry*hv[c].y; }
        #pragma unroll
        for (int o=0;o<Cn;o++){
            float ax=0.f, ay=0.f;
            #pragma unroll
            for (int c=0;c<Cn;c++){
                ax = fmaf(sWc0[o*20+c], xv[c].x, fmaf(sWc0[o*20+10+c], rh[c].x, ax));
                ay = fmaf(sWc0[o*20+c], xv[c].y, fmaf(sWc0[o*20+10+c], rh[c].y, ay));
            }
            float2 r2;
            r2.x = (1.f-ux)*hv[o].x + ux*ftanh(ax);
            r2.y = (1.f-uy)*hv[o].y + uy*ftanh(ay);
            ((float2*)node0)[base+o*HW2] = r2;
        }
    }

    // comp_att + t1 (kept in registers) + BN1 partials
    float2 t1v[2*Cn];
    {
        float2 sv[Cn], fv[Cn];
        float gax=sb[0], gay=sb[0];
        #pragma unroll
        for (int c=0;c<Cn;c++){
            float2 a1v=H1[base+c*HW2], a2v=H2[base+c*HW2];
            gax = fmaf(sWatt[c], a1v.x, fmaf(sWatt[10+c], a2v.x, gax));
            gay = fmaf(sWatt[c], a1v.y, fmaf(sWatt[10+c], a2v.y, gay));
            sv[c].x = a1v.x+a2v.x; sv[c].y = a1v.y+a2v.y;
        }
        float atx = sigm(gax), aty = sigm(gay);
        ((float2*)attOut)[b*HW2+p] = make_float2(atx, aty);
        #pragma unroll
        for (int c=0;c<Cn;c++){
            sv[c].x *= atx; sv[c].y *= aty;
            fv[c] = F1[base+c*HW2];
        }
        #pragma unroll
        for (int o=0;o<2*Cn;o++){
            float tx=0.f, ty=0.f;
            #pragma unroll
            for (int c=0;c<Cn;c++){
                tx = fmaf(sWr1[o*20+c], fv[c].x, fmaf(sWr1[o*20+10+c], sv[c].x, tx));
                ty = fmaf(sWr1[o*20+c], fv[c].y, fmaf(sWr1[o*20+10+c], sv[c].y, ty));
            }
            t1v[o] = make_float2(tx, ty);
            float s = tx+ty, q = fmaf(tx,tx, ty*ty);
            #pragma unroll
            for (int off=16;off;off>>=1){
                s += __shfl_xor_sync(0xffffffffu,s,off);
                q += __shfl_xor_sync(0xffffffffu,q,off);
            }
            if (lane==0){ atomicAdd(&sAcc1[o],s); atomicAdd(&sAcc1[20+o],q); }
        }
    }
    __syncthreads();
    if (tid<40) atomicAdd(&g_s1[tid*64 + (blockIdx.x & 63)], (double)sAcc1[tid]);

    // ================= Barrier 1, BN1 stats (every block, redundant) =================
    grid_barrier(&g_bar[0], tid, true);
    if (tid<40){
        double s=0.0;
        const double* row = &g_s1[tid*64];
        #pragma unroll
        for (int k=0;k<64;k++) s += __ldcg(row+k);
        sStat[tid]=s;
    }
    __syncthreads();
    if (tid<20){
        double m = sStat[tid]    * (1.0/131072.0);
        double v = sStat[20+tid] * (1.0/131072.0) - m*m;
        float a = sGB1[tid] * rsqrtf((float)v + 1e-5f);
        sP1[tid]    = a;
        sP1[20+tid] = sGB1[20+tid] - (float)(a*m);
    }
    __syncthreads();

    // ================= Phase B: y2 = W_r2 @ relu(bn1(t1)) (registers only) =================
    float2 y2v[Cn];
    {
        #pragma unroll
        for (int o=0;o<Cn;o++) y2v[o] = make_float2(0.f,0.f);
        #pragma unroll
        for (int c=0;c<2*Cn;c++){
            float ax = fmaxf(fmaf(sP1[c], t1v[c].x, sP1[20+c]), 0.f);
            float ay = fmaxf(fmaf(sP1[c], t1v[c].y, sP1[20+c]), 0.f);
            #pragma unroll
            for (int o=0;o<Cn;o++){
                y2v[o].x = fmaf(sWr2[o*20+c], ax, y2v[o].x);
                y2v[o].y = fmaf(sWr2[o*20+c], ay, y2v[o].y);
            }
        }
        #pragma unroll
        for (int o=0;o<Cn;o++){
            float s = y2v[o].x + y2v[o].y;
            float q = fmaf(y2v[o].x, y2v[o].x, y2v[o].y*y2v[o].y);
            #pragma unroll
            for (int off=16;off;off>>=1){
                s += __shfl_xor_sync(0xffffffffu,s,off);
                q += __shfl_xor_sync(0xffffffffu,q,off);
            }
            if (lane==0){ atomicAdd(&sAcc2[o],s); atomicAdd(&sAcc2[10+o],q); }
        }
    }
    __syncthreads();
    if (tid<20) atomicAdd(&g_s2[tid*64 + (blockIdx.x & 63)], (double)sAcc2[tid]);

    // ================= Barrier 2, BN2 stats =================
    grid_barrier(&g_bar[1], tid, true);
    // g_s1 dead now: re-zero for next replay (free window)
    if (blockIdx.x < 40 && tid < 64) g_s1[blockIdx.x*64 + tid] = 0.0;
    if (tid<20){
        double s=0.0;
        const double* row = &g_s2[tid*64];
        #pragma unroll
        for (int k=0;k<64;k++) s += __ldcg(row+k);
        sStat[tid]=s;
    }
    __syncthreads();
    if (tid<10){
        double m = sStat[tid]    * (1.0/131072.0);
        double v = sStat[10+tid] * (1.0/131072.0) - m*m;
        float a = sGB2[tid] * rsqrtf((float)v + 1e-5f);
        sP2[tid]    = a;
        sP2[10+tid] = sGB2[10+tid] - (float)(a*m);
    }
    __syncthreads();

    // ================= Phase C: node1 = ConvGRU(x=relu(bn2(y2)), h=f1) =================
    {
        float2 cf[Cn], fv[Cn];
        #pragma unroll
        for (int o=0;o<Cn;o++){
            cf[o].x = fmaxf(fmaf(sP2[o], y2v[o].x, sP2[10+o]), 0.f);
            cf[o].y = fmaxf(fmaf(sP2[o], y2v[o].y, sP2[10+o]), 0.f);
            fv[o] = F1[base + o*HW2];
        }
        float g0x=sb[3], g0y=sb[3], g1x=sb[4], g1y=sb[4];
        #pragma unroll
        for (int c=0;c<Cn;c++){
            g0x = fmaf(sWg1[c],    cf[c].x, fmaf(sWg1[10+c], fv[c].x, g0x));
            g0y = fmaf(sWg1[c],    cf[c].y, fmaf(sWg1[10+c], fv[c].y, g0y));
            g1x = fmaf(sWg1[20+c], cf[c].x, fmaf(sWg1[30+c], fv[c].x, g1x));
            g1y = fmaf(sWg1[20+c], cf[c].y, fmaf(sWg1[30+c], fv[c].y, g1y));
        }
        float rx=sigm(g0x), ry=sigm(g0y), ux=sigm(g1x), uy=sigm(g1y);
        float2 rh[Cn];
        #pragma unroll
        for (int c=0;c<Cn;c++){ rh[c].x = rx*fv[c].x; rh[c].y = ry*fv[c].y; }
        #pragma unroll
        for (int o=0;o<Cn;o++){
            float ax=0.f, ay=0.f;
            #pragma unroll
            for (int c=0;c<Cn;c++){
                ax = fmaf(sWc1[o*20+c], cf[c].x, fmaf(sWc1[o*20+10+c], rh[c].x, ax));
                ay = fmaf(sWc1[o*20+c], cf[c].y, fmaf(sWc1[o*20+10+c], rh[c].y, ay));
            }
            float2 r2;
            r2.x = (1.f-ux)*fv[o].x + ux*ftanh(ax);
            r2.y = (1.f-uy)*fv[o].y + uy*ftanh(ay);
            ((float2*)node1)[base + o*HW2] = r2;
        }
    }

    // ================= Barrier 3 (arrive-only except zeroers), re-zero g_s2 =================
    bool zeroer = (blockIdx.x < 20);
    grid_barrier(&g_bar[2], tid, zeroer);
    if (zeroer && tid < 64) g_s2[blockIdx.x*64 + tid] = 0.0;
}

extern "C" void kernel_launch(void* const* d_in, const int* in_sizes, int n_in,
                              void* d_out, int out_size)
{
    const float* f0    = (const float*)d_in[0];
    const float* f1    = (const float*)d_in[1];
    const float* h0    = (const float*)d_in[2];
    const float* h1    = (const float*)d_in[3];
    const float* h2    = (const float*)d_in[4];
    const float* W_att = (const float*)d_in[5];
    const float* b_att = (const float*)d_in[6];
    const float* W_r1  = (const float*)d_in[7];
    const float* g_r1  = (const float*)d_in[8];
    const float* be_r1 = (const float*)d_in[9];
    const float* W_r2  = (const float*)d_in[10];
    const float* g_r2  = (const float*)d_in[11];
    const float* be_r2 = (const float*)d_in[12];
    const float* Wg0   = (const float*)d_in[13];
    const float* bg0   = (const float*)d_in[14];
    const float* Wc0   = (const float*)d_in[15];
    const float* Wg1   = (const float*)d_in[16];
    const float* bg1   = (const float*)d_in[17];
    const float* Wc1   = (const float*)d_in[18];

    float* out   = (float*)d_out;
    float* node0 = out;                      // [8,10,128,128]
    float* node1 = out + Bn*Cn*HW;           // [8,10,128,128]
    float* att   = out + 2*Bn*Cn*HW;         // [8,1,128,128]

    k_fused<<<NBL, NTH>>>(f0, f1, h0, h1, h2,
                          W_att, b_att,
                          W_r1, g_r1, be_r1,
                          W_r2, g_r2, be_r2,
                          Wg0, bg0, Wc0, Wg1, bg1, Wc1,
                          node0, node1, att);
}

// round 6
// speedup vs baseline: 1.3636x; 1.3636x over previous
#include <cuda_runtime.h>

#define HW    16384
#define HW2   8192
#define Bn    8
#define Cn    10
#define NTH   128
#define NBL   512          // NBL*NTH threads, 2 px each = 131072 px

// Persistent scratch (allocation-free)
__device__ double   g_s1[40*64];   // BN1 slot partials: rows 0..19 sum, 20..39 sumsq
__device__ double   g_s2[20*64];   // BN2 slot partials
__device__ unsigned g_bar[3];      // monotonic barrier counters (never reset)

__device__ __forceinline__ float sigm(float x){ return 1.f/(1.f+__expf(-x)); }
__device__ __forceinline__ float ftanh(float x){ return fmaf(2.f, 1.f/(1.f+__expf(-2.f*x)), -1.f); }

// Monotonic ticket barrier. wait=false: arrive-only (no spin).
__device__ __forceinline__ void grid_barrier(unsigned* ctr, int tid, bool wait){
    __syncthreads();
    if (tid == 0){
        __threadfence();
        unsigned ticket = atomicAdd(ctr, 1u);
        if (wait){
            unsigned target = (ticket / NBL + 1u) * NBL;
            while ((int)(*(volatile unsigned*)ctr - target) < 0) __nanosleep(32);
            __threadfence();
        }
    }
    __syncthreads();
}

__global__ void __launch_bounds__(NTH, 4) k_fused(
    const float* __restrict__ f0, const float* __restrict__ f1,
    const float* __restrict__ h0, const float* __restrict__ h1, const float* __restrict__ h2,
    const float* __restrict__ W_att, const float* __restrict__ b_att,
    const float* __restrict__ W_r1,  const float* __restrict__ g_r1, const float* __restrict__ be_r1,
    const float* __restrict__ W_r2,  const float* __restrict__ g_r2, const float* __restrict__ be_r2,
    const float* __restrict__ Wg0, const float* __restrict__ bg0, const float* __restrict__ Wc0,
    const float* __restrict__ Wg1, const float* __restrict__ bg1, const float* __restrict__ Wc1,
    float* __restrict__ node0, float* __restrict__ node1, float* __restrict__ attOut)
{
    __shared__ float sWg0[40], sWc0[200], sWatt[20], sWr1[400];
    __shared__ float sWr2[200], sWg1[40], sWc1[200];
    __shared__ float sGB1[40], sGB2[20];
    __shared__ float sb[5];                  // b_att, bg0[0..1], bg1[0..1]
    __shared__ float sAcc1[40], sAcc2[20];
    __shared__ double sStat[40];
    __shared__ float sP1[40], sP2[20];
    __shared__ float2 sT1[2*Cn][NTH];        // t1 staging: 20 ch x 128 threads (20.5 KB)

    int tid = threadIdx.x;
    for (int i=tid;i<40;i+=NTH)  sWg0[i]=Wg0[i];
    for (int i=tid;i<200;i+=NTH) sWc0[i]=Wc0[i];
    for (int i=tid;i<20;i+=NTH)  sWatt[i]=W_att[i];
    for (int i=tid;i<400;i+=NTH) sWr1[i]=W_r1[i];
    for (int i=tid;i<200;i+=NTH) sWr2[i]=W_r2[i];
    for (int i=tid;i<40;i+=NTH)  sWg1[i]=Wg1[i];
    for (int i=tid;i<200;i+=NTH) sWc1[i]=Wc1[i];
    if (tid<20){ sGB1[tid]=g_r1[tid]; sGB1[20+tid]=be_r1[tid]; }
    if (tid<10){ sGB2[tid]=g_r2[tid]; sGB2[10+tid]=be_r2[tid]; }
    if (tid==0){ sb[0]=b_att[0]; sb[1]=bg0[0]; sb[2]=bg0[1]; sb[3]=bg1[0]; sb[4]=bg1[1]; }
    if (tid<40) sAcc1[tid]=0.f;
    if (tid<20) sAcc2[tid]=0.f;
    __syncthreads();

    int idx = blockIdx.x*NTH + tid;      // float2 index
    int b = idx >> 13, p = idx & (HW2-1);
    long base = (long)b*Cn*HW2 + p;
    int lane = tid & 31;

    const float2* F0 = (const float2*)f0;
    const float2* F1 = (const float2*)f1;
    const float2* H0 = (const float2*)h0;
    const float2* H1 = (const float2*)h1;
    const float2* H2 = (const float2*)h2;

    // ================= Phase A1: node0 = ConvGRU(x=h0, h=f0) =================
    {
        float2 xv[Cn], hv[Cn];
        #pragma unroll
        for (int c=0;c<Cn;c++){ xv[c]=H0[base+c*HW2]; hv[c]=F0[base+c*HW2]; }
        float g0x=sb[1], g0y=sb[1], g1x=sb[2], g1y=sb[2];
        #pragma unroll
        for (int c=0;c<Cn;c++){
            g0x = fmaf(sWg0[c],    xv[c].x, fmaf(sWg0[10+c], hv[c].x, g0x));
            g0y = fmaf(sWg0[c],    xv[c].y, fmaf(sWg0[10+c], hv[c].y, g0y));
            g1x = fmaf(sWg0[20+c], xv[c].x, fmaf(sWg0[30+c], hv[c].x, g1x));
            g1y = fmaf(sWg0[20+c], xv[c].y, fmaf(sWg0[30+c], hv[c].y, g1y));
        }
        float rx=sigm(g0x), ry=sigm(g0y), ux=sigm(g1x), uy=sigm(g1y);
        float2 rh[Cn];
        #pragma unroll
        for (int c=0;c<Cn;c++){ rh[c].x = rx*hv[c].x; rh[c].y = ry*hv[c].y; }
        #pragma unroll
        for (int o=0;o<Cn;o++){
            float ax=0.f, ay=0.f;
            #pragma unroll
            for (int c=0;c<Cn;c++){
                ax = fmaf(sWc0[o*20+c], xv[c].x, fmaf(sWc0[o*20+10+c], rh[c].x, ax));
                ay = fmaf(sWc0[o*20+c], xv[c].y, fmaf(sWc0[o*20+10+c], rh[c].y, ay));
            }
            float2 r2;
            r2.x = (1.f-ux)*hv[o].x + ux*ftanh(ax);
            r2.y = (1.f-uy)*hv[o].y + uy*ftanh(ay);
            ((float2*)node0)[base+o*HW2] = r2;
        }
    }

    // ================= Phase A2: comp_att + t1 (-> smem) + BN1 partials =================
    {
        float2 sv[Cn], fv[Cn];
        float gax=sb[0], gay=sb[0];
        #pragma unroll
        for (int c=0;c<Cn;c++){
            float2 a1v=H1[base+c*HW2], a2v=H2[base+c*HW2];
            gax = fmaf(sWatt[c], a1v.x, fmaf(sWatt[10+c], a2v.x, gax));
            gay = fmaf(sWatt[c], a1v.y, fmaf(sWatt[10+c], a2v.y, gay));
            sv[c].x = a1v.x+a2v.x; sv[c].y = a1v.y+a2v.y;
        }
        float atx = sigm(gax), aty = sigm(gay);
        ((float2*)attOut)[b*HW2+p] = make_float2(atx, aty);
        #pragma unroll
        for (int c=0;c<Cn;c++){
            sv[c].x *= atx; sv[c].y *= aty;
            fv[c] = F1[base+c*HW2];
        }
        #pragma unroll
        for (int o=0;o<2*Cn;o++){
            float tx=0.f, ty=0.f;
            #pragma unroll
            for (int c=0;c<Cn;c++){
                tx = fmaf(sWr1[o*20+c], fv[c].x, fmaf(sWr1[o*20+10+c], sv[c].x, tx));
                ty = fmaf(sWr1[o*20+c], fv[c].y, fmaf(sWr1[o*20+10+c], sv[c].y, ty));
            }
            sT1[o][tid] = make_float2(tx, ty);
            float s = tx+ty, q = fmaf(tx,tx, ty*ty);
            #pragma unroll
            for (int off=16;off;off>>=1){
                s += __shfl_xor_sync(0xffffffffu,s,off);
                q += __shfl_xor_sync(0xffffffffu,q,off);
            }
            if (lane==0){ atomicAdd(&sAcc1[o],s); atomicAdd(&sAcc1[20+o],q); }
        }
    }
    __syncthreads();
    if (tid<40) atomicAdd(&g_s1[tid*64 + (blockIdx.x & 63)], (double)sAcc1[tid]);

    // ================= Barrier 1, BN1 stats (every block, redundant) =================
    grid_barrier(&g_bar[0], tid, true);
    if (tid<40){
        double s=0.0;
        const double* row = &g_s1[tid*64];
        #pragma unroll
        for (int k=0;k<64;k++) s += __ldcg(row+k);
        sStat[tid]=s;
    }
    __syncthreads();
    if (tid<20){
        double m = sStat[tid]    * (1.0/131072.0);
        double v = sStat[20+tid] * (1.0/131072.0) - m*m;
        float a = sGB1[tid] * rsqrtf((float)v + 1e-5f);
        sP1[tid]    = a;
        sP1[20+tid] = sGB1[20+tid] - (float)(a*m);
    }
    __syncthreads();

    // ================= Phase B: y2 = W_r2 @ relu(bn1(t1)), y2 in regs =================
    float2 y2v[Cn];
    {
        #pragma unroll
        for (int o=0;o<Cn;o++) y2v[o] = make_float2(0.f,0.f);
        #pragma unroll
        for (int c=0;c<2*Cn;c++){
            float2 t = sT1[c][tid];
            float ax = fmaxf(fmaf(sP1[c], t.x, sP1[20+c]), 0.f);
            float ay = fmaxf(fmaf(sP1[c], t.y, sP1[20+c]), 0.f);
            #pragma unroll
            for (int o=0;o<Cn;o++){
                y2v[o].x = fmaf(sWr2[o*20+c], ax, y2v[o].x);
                y2v[o].y = fmaf(sWr2[o*20+c], ay, y2v[o].y);
            }
        }
        #pragma unroll
        for (int o=0;o<Cn;o++){
            float s = y2v[o].x + y2v[o].y;
            float q = fmaf(y2v[o].x, y2v[o].x, y2v[o].y*y2v[o].y);
            #pragma unroll
            for (int off=16;off;off>>=1){
                s += __shfl_xor_sync(0xffffffffu,s,off);
                q += __shfl_xor_sync(0xffffffffu,q,off);
            }
            if (lane==0){ atomicAdd(&sAcc2[o],s); atomicAdd(&sAcc2[10+o],q); }
        }
    }
    __syncthreads();
    if (tid<20) atomicAdd(&g_s2[tid*64 + (blockIdx.x & 63)], (double)sAcc2[tid]);

    // ================= Barrier 2, BN2 stats =================
    grid_barrier(&g_bar[1], tid, true);
    // g_s1 dead now: re-zero for next replay (free window)
    if (blockIdx.x < 40 && tid < 64) g_s1[blockIdx.x*64 + tid] = 0.0;
    if (tid<20){
        double s=0.0;
        const double* row = &g_s2[tid*64];
        #pragma unroll
        for (int k=0;k<64;k++) s += __ldcg(row+k);
        sStat[tid]=s;
    }
    __syncthreads();
    if (tid<10){
        double m = sStat[tid]    * (1.0/131072.0);
        double v = sStat[10+tid] * (1.0/131072.0) - m*m;
        float a = sGB2[tid] * rsqrtf((float)v + 1e-5f);
        sP2[tid]    = a;
        sP2[10+tid] = sGB2[10+tid] - (float)(a*m);
    }
    __syncthreads();

    // ================= Phase C: node1 = ConvGRU(x=relu(bn2(y2)), h=f1) =================
    {
        float2 cf[Cn], fv[Cn];
        #pragma unroll
        for (int o=0;o<Cn;o++){
            cf[o].x = fmaxf(fmaf(sP2[o], y2v[o].x, sP2[10+o]), 0.f);
            cf[o].y = fmaxf(fmaf(sP2[o], y2v[o].y, sP2[10+o]), 0.f);
            fv[o] = F1[base + o*HW2];
        }
        float g0x=sb[3], g0y=sb[3], g1x=sb[4], g1y=sb[4];
        #pragma unroll
        for (int c=0;c<Cn;c++){
            g0x = fmaf(sWg1[c],    cf[c].x, fmaf(sWg1[10+c], fv[c].x, g0x));
            g0y = fmaf(sWg1[c],    cf[c].y, fmaf(sWg1[10+c], fv[c].y, g0y));
            g1x = fmaf(sWg1[20+c], cf[c].x, fmaf(sWg1[30+c], fv[c].x, g1x));
            g1y = fmaf(sWg1[20+c], cf[c].y, fmaf(sWg1[30+c], fv[c].y, g1y));
        }
        float rx=sigm(g0x), ry=sigm(g0y), ux=sigm(g1x), uy=sigm(g1y);
        float2 rh[Cn];
        #pragma unroll
        for (int c=0;c<Cn;c++){ rh[c].x = rx*fv[c].x; rh[c].y = ry*fv[c].y; }
        #pragma unroll
        for (int o=0;o<Cn;o++){
            float ax=0.f, ay=0.f;
            #pragma unroll
            for (int c=0;c<Cn;c++){
                ax = fmaf(sWc1[o*20+c], cf[c].x, fmaf(sWc1[o*20+10+c], rh[c].x, ax));
                ay = fmaf(sWc1[o*20+c], cf[c].y, fmaf(sWc1[o*20+10+c], rh[c].y, ay));
            }
            float2 r2;
            r2.x = (1.f-ux)*fv[o].x + ux*ftanh(ax);
            r2.y = (1.f-uy)*fv[o].y + uy*ftanh(ay);
            ((float2*)node1)[base + o*HW2] = r2;
        }
    }

    // ================= Barrier 3 (arrive-only except zeroers), re-zero g_s2 =================
    bool zeroer = (blockIdx.x < 20);
    grid_barrier(&g_bar[2], tid, zeroer);
    if (zeroer && tid < 64) g_s2[blockIdx.x*64 + tid] = 0.0;
}

extern "C" void kernel_launch(void* const* d_in, const int* in_sizes, int n_in,
                              void* d_out, int out_size)
{
    const float* f0    = (const float*)d_in[0];
    const float* f1    = (const float*)d_in[1];
    const float* h0    = (const float*)d_in[2];
    const float* h1    = (const float*)d_in[3];
    const float* h2    = (const float*)d_in[4];
    const float* W_att = (const float*)d_in[5];
    const float* b_att = (const float*)d_in[6];
    const float* W_r1  = (const float*)d_in[7];
    const float* g_r1  = (const float*)d_in[8];
    const float* be_r1 = (const float*)d_in[9];
    const float* W_r2  = (const float*)d_in[10];
    const float* g_r2  = (const float*)d_in[11];
    const float* be_r2 = (const float*)d_in[12];
    const float* Wg0   = (const float*)d_in[13];
    const float* bg0   = (const float*)d_in[14];
    const float* Wc0   = (const float*)d_in[15];
    const float* Wg1   = (const float*)d_in[16];
    const float* bg1   = (const float*)d_in[17];
    const float* Wc1   = (const float*)d_in[18];

    float* out   = (float*)d_out;
    float* node0 = out;                      // [8,10,128,128]
    float* node1 = out + Bn*Cn*HW;           // [8,10,128,128]
    float* att   = out + 2*Bn*Cn*HW;         // [8,1,128,128]

    k_fused<<<NBL, NTH>>>(f0, f1, h0, h1, h2,
                          W_att, b_att,
                          W_r1, g_r1, be_r1,
                          W_r2, g_r2, be_r2,
                          Wg0, bg0, Wc0, Wg1, bg1, Wc1,
                          node0, node1, att);
}

// round 7
// speedup vs baseline: 1.6550x; 1.2137x over previous
#include <cuda_runtime.h>

#define HW    16384
#define Bn    8
#define Cn    10
#define NP    (Bn*HW)       // 131072 pixels
#define NTH   256
#define NBL   (NP/NTH)      // 512 blocks
#define NSLOT 32

// Persistent scratch (allocation-free)
__device__ double   g_s1[40*NSLOT];   // BN1 partials: ch 0..19 sum, 20..39 sumsq
__device__ double   g_s2[20*NSLOT];   // BN2 partials
__device__ float    g_p1[40];         // BN1 folded scale/shift
__device__ float    g_p2[20];         // BN2 folded scale/shift
__device__ unsigned g_cnt1, g_cnt2;   // last-block tickets (reset by last block)
__device__ float    g_t1[Bn*2*Cn*HW]; // conv1 pre-BN [b,20,hw]
__device__ float    g_y2[Bn*Cn*HW];   // conv2 pre-BN [b,10,hw]

__device__ __forceinline__ float sigm(float x){ return 1.f/(1.f+__expf(-x)); }
__device__ __forceinline__ float ftanh(float x){ return fmaf(2.f, 1.f/(1.f+__expf(-2.f*x)), -1.f); }

// ===== Pass A: node0 GRU, comp_att, t1, BN1 partials + last-block fold =====
__global__ void __launch_bounds__(NTH) k_passA(
    const float* __restrict__ f0, const float* __restrict__ h0,
    const float* __restrict__ f1, const float* __restrict__ h1, const float* __restrict__ h2,
    const float* __restrict__ W_att, const float* __restrict__ b_att,
    const float* __restrict__ W_r1,  const float* __restrict__ g_r1, const float* __restrict__ be_r1,
    const float* __restrict__ Wg0, const float* __restrict__ bg0, const float* __restrict__ Wc0,
    float* __restrict__ node0, float* __restrict__ attOut)
{
    __shared__ float sWg0[40], sWc0[200], sWatt[20], sWr1[400], sb[3];
    __shared__ float sAcc[40];
    __shared__ double sStat[40];
    __shared__ bool sLast;
    int tid = threadIdx.x;
    for (int i=tid;i<40;i+=NTH)  sWg0[i]=Wg0[i];
    for (int i=tid;i<200;i+=NTH) sWc0[i]=Wc0[i];
    for (int i=tid;i<20;i+=NTH)  sWatt[i]=W_att[i];
    for (int i=tid;i<400;i+=NTH) sWr1[i]=W_r1[i];
    if (tid==0){ sb[0]=b_att[0]; sb[1]=bg0[0]; sb[2]=bg0[1]; }
    if (tid<40) sAcc[tid]=0.f;
    __syncthreads();

    int idx = blockIdx.x*NTH + tid;
    int b = idx >> 14, p = idx & (HW-1);
    int base = b*Cn*HW + p;
    int lane = tid & 31;

    // node0 = ConvGRU(x=h0, h=f0)
    {
        float xv[Cn], hv[Cn];
        #pragma unroll
        for (int c=0;c<Cn;c++){ xv[c]=h0[base+c*HW]; hv[c]=f0[base+c*HW]; }
        float g0=sb[1], g1=sb[2];
        #pragma unroll
        for (int c=0;c<Cn;c++){
            g0 = fmaf(sWg0[c],    xv[c], fmaf(sWg0[10+c], hv[c], g0));
            g1 = fmaf(sWg0[20+c], xv[c], fmaf(sWg0[30+c], hv[c], g1));
        }
        float r = sigm(g0), u = sigm(g1);
        #pragma unroll
        for (int o=0;o<Cn;o++){
            float a=0.f;
            #pragma unroll
            for (int c=0;c<Cn;c++)
                a = fmaf(sWc0[o*20+c], xv[c], fmaf(sWc0[o*20+10+c], r*hv[c], a));
            node0[base+o*HW] = (1.f-u)*hv[o] + u*ftanh(a);
        }
    }

    // comp_att + t1 + BN1 partials
    {
        float sv[Cn], fv[Cn];
        float ga = sb[0];
        #pragma unroll
        for (int c=0;c<Cn;c++){
            float a1v=h1[base+c*HW], a2v=h2[base+c*HW];
            ga = fmaf(sWatt[c], a1v, fmaf(sWatt[10+c], a2v, ga));
            sv[c]=a1v+a2v;
        }
        float att = sigm(ga);
        attOut[b*HW+p] = att;
        #pragma unroll
        for (int c=0;c<Cn;c++){ sv[c]*=att; fv[c]=f1[base+c*HW]; }
        #pragma unroll
        for (int o=0;o<2*Cn;o++){
            float t=0.f;
            #pragma unroll
            for (int c=0;c<Cn;c++)
                t = fmaf(sWr1[o*20+c], fv[c], fmaf(sWr1[o*20+10+c], sv[c], t));
            g_t1[(b*2*Cn+o)*HW + p] = t;
            float s=t, q=t*t;
            #pragma unroll
            for (int off=16;off;off>>=1){
                s += __shfl_xor_sync(0xffffffffu,s,off);
                q += __shfl_xor_sync(0xffffffffu,q,off);
            }
            if (lane==0){ atomicAdd(&sAcc[o],s); atomicAdd(&sAcc[20+o],q); }
        }
    }
    __syncthreads();
    if (tid<40) atomicAdd(&g_s1[tid*NSLOT + (blockIdx.x & (NSLOT-1))], (double)sAcc[tid]);
    __threadfence();
    __syncthreads();
    if (tid==0) sLast = (atomicAdd(&g_cnt1, 1u) == NBL-1);
    __syncthreads();
    if (sLast){
        if (tid<40){
            double s=0.0;
            #pragma unroll
            for (int k=0;k<NSLOT;k++){ s += g_s1[tid*NSLOT+k]; g_s1[tid*NSLOT+k]=0.0; }
            sStat[tid]=s;
        }
        __syncthreads();
        if (tid<20){
            double m = sStat[tid]    * (1.0/(double)NP);
            double v = sStat[20+tid] * (1.0/(double)NP) - m*m;
            float a = g_r1[tid] * rsqrtf((float)v + 1e-5f);
            g_p1[tid]    = a;
            g_p1[20+tid] = be_r1[tid] - (float)(a*m);
        }
        if (tid==0) g_cnt1 = 0u;
    }
}

// ===== Pass B: y2 = W_r2 @ relu(bn1(t1)), BN2 partials + last-block fold =====
__global__ void __launch_bounds__(NTH) k_passB(
    const float* __restrict__ W_r2, const float* __restrict__ g_r2, const float* __restrict__ be_r2)
{
    __shared__ float sW[200], sP[40], sAcc[20];
    __shared__ double sStat[20];
    __shared__ bool sLast;
    int tid = threadIdx.x;
    for (int i=tid;i<200;i+=NTH) sW[i]=W_r2[i];
    if (tid<40) sP[tid]=g_p1[tid];
    if (tid<20) sAcc[tid]=0.f;
    __syncthreads();

    int idx = blockIdx.x*NTH + tid;
    int b = idx >> 14, p = idx & (HW-1);
    int lane = tid & 31;

    float y[Cn];
    #pragma unroll
    for (int o=0;o<Cn;o++) y[o]=0.f;
    int tbase = b*2*Cn*HW + p;
    #pragma unroll
    for (int c=0;c<2*Cn;c++){
        float t = g_t1[tbase + c*HW];
        float x = fmaxf(fmaf(sP[c], t, sP[20+c]), 0.f);
        #pragma unroll
        for (int o=0;o<Cn;o++) y[o] = fmaf(sW[o*20+c], x, y[o]);
    }
    int ybase = b*Cn*HW + p;
    #pragma unroll
    for (int o=0;o<Cn;o++){
        g_y2[ybase + o*HW] = y[o];
        float s=y[o], q=y[o]*y[o];
        #pragma unroll
        for (int off=16;off;off>>=1){
            s += __shfl_xor_sync(0xffffffffu,s,off);
            q += __shfl_xor_sync(0xffffffffu,q,off);
        }
        if (lane==0){ atomicAdd(&sAcc[o],s); atomicAdd(&sAcc[10+o],q); }
    }
    __syncthreads();
    if (tid<20) atomicAdd(&g_s2[tid*NSLOT + (blockIdx.x & (NSLOT-1))], (double)sAcc[tid]);
    __threadfence();
    __syncthreads();
    if (tid==0) sLast = (atomicAdd(&g_cnt2, 1u) == NBL-1);
    __syncthreads();
    if (sLast){
        if (tid<20){
            double s=0.0;
            #pragma unroll
            for (int k=0;k<NSLOT;k++){ s += g_s2[tid*NSLOT+k]; g_s2[tid*NSLOT+k]=0.0; }
            sStat[tid]=s;
        }
        __syncthreads();
        if (tid<10){
            double m = sStat[tid]    * (1.0/(double)NP);
            double v = sStat[10+tid] * (1.0/(double)NP) - m*m;
            float a = g_r2[tid] * rsqrtf((float)v + 1e-5f);
            g_p2[tid]    = a;
            g_p2[10+tid] = be_r2[tid] - (float)(a*m);
        }
        if (tid==0) g_cnt2 = 0u;
    }
}

// ===== Pass C: node1 = ConvGRU(x=relu(bn2(y2)), h=f1) =====
__global__ void __launch_bounds__(NTH) k_passC(
    const float* __restrict__ f1,
    const float* __restrict__ Wg1, const float* __restrict__ bg1, const float* __restrict__ Wc1,
    float* __restrict__ node1)
{
    __shared__ float sWg[40], sWc[200], sP[20], sbg[2];
    int tid = threadIdx.x;
    for (int i=tid;i<40;i+=NTH)  sWg[i]=Wg1[i];
    for (int i=tid;i<200;i+=NTH) sWc[i]=Wc1[i];
    if (tid<20) sP[tid]=g_p2[tid];
    if (tid==0){ sbg[0]=bg1[0]; sbg[1]=bg1[1]; }
    __syncthreads();

    int idx = blockIdx.x*NTH + tid;
    int b = idx >> 14, p = idx & (HW-1);
    int base = b*Cn*HW + p;

    float cf[Cn], fv[Cn];
    #pragma unroll
    for (int o=0;o<Cn;o++){
        float yv = g_y2[base + o*HW];
        cf[o] = fmaxf(fmaf(sP[o], yv, sP[10+o]), 0.f);
        fv[o] = f1[base + o*HW];
    }
    float g0=sbg[0], g1=sbg[1];
    #pragma unroll
    for (int c=0;c<Cn;c++){
        g0 = fmaf(sWg[c],    cf[c], fmaf(sWg[10+c], fv[c], g0));
        g1 = fmaf(sWg[20+c], cf[c], fmaf(sWg[30+c], fv[c], g1));
    }
    float r = sigm(g0), u = sigm(g1);
    #pragma unroll
    for (int o=0;o<Cn;o++){
        float a=0.f;
        #pragma unroll
        for (int c=0;c<Cn;c++)
            a = fmaf(sWc[o*20+c], cf[c], fmaf(sWc[o*20+10+c], r*fv[c], a));
        node1[base+o*HW] = (1.f-u)*fv[o] + u*ftanh(a);
    }
}

extern "C" void kernel_launch(void* const* d_in, const int* in_sizes, int n_in,
                              void* d_out, int out_size)
{
    const float* f0    = (const float*)d_in[0];
    const float* f1    = (const float*)d_in[1];
    const float* h0    = (const float*)d_in[2];
    const float* h1    = (const float*)d_in[3];
    const float* h2    = (const float*)d_in[4];
    const float* W_att = (const float*)d_in[5];
    const float* b_att = (const float*)d_in[6];
    const float* W_r1  = (const float*)d_in[7];
    const float* g_r1  = (const float*)d_in[8];
    const float* be_r1 = (const float*)d_in[9];
    const float* W_r2  = (const float*)d_in[10];
    const float* g_r2  = (const float*)d_in[11];
    const float* be_r2 = (const float*)d_in[12];
    const float* Wg0   = (const float*)d_in[13];
    const float* bg0   = (const float*)d_in[14];
    const float* Wc0   = (const float*)d_in[15];
    const float* Wg1   = (const float*)d_in[16];
    const float* bg1   = (const float*)d_in[17];
    const float* Wc1   = (const float*)d_in[18];

    float* out   = (float*)d_out;
    float* node0 = out;                      // [8,10,128,128]
    float* node1 = out + Bn*Cn*HW;           // [8,10,128,128]
    float* att   = out + 2*Bn*Cn*HW;         // [8,1,128,128]

    k_passA<<<NBL, NTH>>>(f0, h0, f1, h1, h2, W_att, b_att,
                          W_r1, g_r1, be_r1, Wg0, bg0, Wc0, node0, att);
    k_passB<<<NBL, NTH>>>(W_r2, g_r2, be_r2);
    k_passC<<<NBL, NTH>>>(f1, Wg1, bg1, Wc1, node1);
}

// round 9
// speedup vs baseline: 2.9596x; 1.7883x over previous
#include <cuda_runtime.h>

#define HW    16384
#define Bn    8
#define Cn    10
#define NP    (Bn*HW)       // 131072 pixels
#define NTH   256
#define NBL   (NP/NTH)      // 512 blocks per pixel-cover
#define NSLOT 32

// Persistent scratch (allocation-free)
__device__ double   g_s1[40*NSLOT];   // BN1 partials: rows 0..19 sum, 20..39 sumsq
__device__ double   g_s2[20*NSLOT];   // BN2 partials
__device__ float    g_p1[40];         // BN1 folded scale/shift
__device__ float    g_p2[20];         // BN2 folded scale/shift
__device__ unsigned g_cnt1, g_cnt2;   // last-block tickets (reset by last block)
__device__ float    g_t1[Bn*2*Cn*HW]; // conv1 pre-BN [b,20,hw]
__device__ float    g_y2[Bn*Cn*HW];   // conv2 pre-BN [b,10,hw]

__device__ __forceinline__ float sigm(float x){ return 1.f/(1.f+__expf(-x)); }
__device__ __forceinline__ float ftanh(float x){ return fmaf(2.f, 1.f/(1.f+__expf(-2.f*x)), -1.f); }

// ===== Pass A: 1024 blocks. Role 0 (bid<512): node0 GRU. Role 1: att + t1 + BN1 stats =====
__global__ void __launch_bounds__(NTH) k_passA(
    const float* __restrict__ f0, const float* __restrict__ h0,
    const float* __restrict__ f1, const float* __restrict__ h1, const float* __restrict__ h2,
    const float* __restrict__ W_att, const float* __restrict__ b_att,
    const float* __restrict__ W_r1,  const float* __restrict__ g_r1, const float* __restrict__ be_r1,
    const float* __restrict__ Wg0, const float* __restrict__ bg0, const float* __restrict__ Wc0,
    float* __restrict__ node0, float* __restrict__ attOut)
{
    __shared__ float sWg0[40], sWc0[200];        // role 0
    __shared__ float sWatt[20], sWr1[400];       // role 1
    __shared__ float sT[2*Cn][NTH];              // role 1 staging (20 KB)
    __shared__ float sb[3];
    __shared__ double sStat[40];
    __shared__ bool sLast;

    int tid  = threadIdx.x;
    int lane = tid & 31;
    int w    = tid >> 5;
    int bid  = blockIdx.x & (NBL-1);
    int role = blockIdx.x >> 9;

    int idx = bid*NTH + tid;
    int b = idx >> 14, p = idx & (HW-1);
    int base = b*Cn*HW + p;

    if (role == 0){
        // ---------- node0 = ConvGRU(x=h0, h=f0) ----------
        for (int i=tid;i<40;i+=NTH)  sWg0[i]=Wg0[i];
        for (int i=tid;i<200;i+=NTH) sWc0[i]=Wc0[i];
        if (tid==0){ sb[1]=bg0[0]; sb[2]=bg0[1]; }
        __syncthreads();

        float xv[Cn], hv[Cn];
        #pragma unroll
        for (int c=0;c<Cn;c++){ xv[c]=h0[base+c*HW]; hv[c]=f0[base+c*HW]; }
        float g0=sb[1], g1=sb[2];
        #pragma unroll
        for (int c=0;c<Cn;c++){
            g0 = fmaf(sWg0[c],    xv[c], fmaf(sWg0[10+c], hv[c], g0));
            g1 = fmaf(sWg0[20+c], xv[c], fmaf(sWg0[30+c], hv[c], g1));
        }
        float r = sigm(g0), u = sigm(g1);
        #pragma unroll
        for (int o=0;o<Cn;o++){
            float a=0.f;
            #pragma unroll
            for (int c=0;c<Cn;c++)
                a = fmaf(sWc0[o*20+c], xv[c], fmaf(sWc0[o*20+10+c], r*hv[c], a));
            node0[base+o*HW] = (1.f-u)*hv[o] + u*ftanh(a);
        }
    } else {
        // ---------- comp_att + t1 + BN1 partials ----------
        for (int i=tid;i<20;i+=NTH)  sWatt[i]=W_att[i];
        for (int i=tid;i<400;i+=NTH) sWr1[i]=W_r1[i];
        if (tid==0) sb[0]=b_att[0];
        __syncthreads();

        float sv[Cn], fv[Cn];
        float ga = sb[0];
        #pragma unroll
        for (int c=0;c<Cn;c++){
            float a1v=h1[base+c*HW], a2v=h2[base+c*HW];
            ga = fmaf(sWatt[c], a1v, fmaf(sWatt[10+c], a2v, ga));
            sv[c]=a1v+a2v;
        }
        float att = sigm(ga);
        attOut[b*HW+p] = att;
        #pragma unroll
        for (int c=0;c<Cn;c++){ sv[c]*=att; fv[c]=f1[base+c*HW]; }
        #pragma unroll
        for (int o=0;o<2*Cn;o++){
            float t=0.f;
            #pragma unroll
            for (int c=0;c<Cn;c++)
                t = fmaf(sWr1[o*20+c], fv[c], fmaf(sWr1[o*20+10+c], sv[c], t));
            g_t1[(b*2*Cn+o)*HW + p] = t;
            sT[o][tid] = t;
        }
        __syncthreads();

        // warp-per-channel reduction: warp w handles ch w, w+8, w+16(<20)
        int slot = bid & (NSLOT-1);
        #pragma unroll
        for (int k=0;k<3;k++){
            int ch = w + k*8;
            if (ch < 2*Cn){
                float s=0.f, q=0.f;
                #pragma unroll
                for (int j=0;j<NTH/32;j++){
                    float v = sT[ch][j*32+lane];
                    s += v; q = fmaf(v,v,q);
                }
                #pragma unroll
                for (int off=16;off;off>>=1){
                    s += __shfl_xor_sync(0xffffffffu,s,off);
                    q += __shfl_xor_sync(0xffffffffu,q,off);
                }
                if (lane==0){
                    atomicAdd(&g_s1[ch*NSLOT+slot],      (double)s);
                    atomicAdd(&g_s1[(20+ch)*NSLOT+slot], (double)q);
                }
            }
        }
        __threadfence();
        __syncthreads();
        if (tid==0) sLast = (atomicAdd(&g_cnt1, 1u) == NBL-1);
        __syncthreads();
        if (sLast){
            if (tid<40){
                double s=0.0;
                #pragma unroll
                for (int k=0;k<NSLOT;k++){
                    s += __ldcg(&g_s1[tid*NSLOT+k]);
                    g_s1[tid*NSLOT+k]=0.0;
                }
                sStat[tid]=s;
            }
            __syncthreads();
            if (tid<20){
                double m = sStat[tid]    * (1.0/(double)NP);
                double v = sStat[20+tid] * (1.0/(double)NP) - m*m;
                float a = g_r1[tid] * rsqrtf((float)v + 1e-5f);
                g_p1[tid]    = a;
                g_p1[20+tid] = be_r1[tid] - (float)(a*m);
            }
            if (tid==0) g_cnt1 = 0u;
        }
    }
}

// ===== Pass B: y2 = W_r2 @ relu(bn1(t1)), BN2 partials + last-block fold =====
__global__ void __launch_bounds__(NTH) k_passB(
    const float* __restrict__ W_r2, const float* __restrict__ g_r2, const float* __restrict__ be_r2)
{
    __shared__ float sW[200], sP[40];
    __shared__ float sY[Cn][NTH];      // 10 KB
    __shared__ double sStat[20];
    __shared__ bool sLast;
    int tid = threadIdx.x;
    int lane = tid & 31;
    int w = tid >> 5;
    for (int i=tid;i<200;i+=NTH) sW[i]=W_r2[i];
    if (tid<40) sP[tid]=g_p1[tid];
    __syncthreads();

    int idx = blockIdx.x*NTH + tid;
    int b = idx >> 14, p = idx & (HW-1);

    float y[Cn];
    #pragma unroll
    for (int o=0;o<Cn;o++) y[o]=0.f;
    int tbase = b*2*Cn*HW + p;
    #pragma unroll
    for (int c=0;c<2*Cn;c++){
        float t = g_t1[tbase + c*HW];
        float x = fmaxf(fmaf(sP[c], t, sP[20+c]), 0.f);
        #pragma unroll
        for (int o=0;o<Cn;o++) y[o] = fmaf(sW[o*20+c], x, y[o]);
    }
    int ybase = b*Cn*HW + p;
    #pragma unroll
    for (int o=0;o<Cn;o++){
        g_y2[ybase + o*HW] = y[o];
        sY[o][tid] = y[o];
    }
    __syncthreads();

    // warp-per-channel reduction: warp w handles ch w, and w<2 also ch 8+w
    int slot = blockIdx.x & (NSLOT-1);
    #pragma unroll
    for (int k=0;k<2;k++){
        int ch = w + k*8;
        if (ch < Cn){
            float s=0.f, q=0.f;
            #pragma unroll
            for (int j=0;j<NTH/32;j++){
                float v = sY[ch][j*32+lane];
                s += v; q = fmaf(v,v,q);
            }
            #pragma unroll
            for (int off=16;off;off>>=1){
                s += __shfl_xor_sync(0xffffffffu,s,off);
                q += __shfl_xor_sync(0xffffffffu,q,off);
            }
            if (lane==0){
                atomicAdd(&g_s2[ch*NSLOT+slot],      (double)s);
                atomicAdd(&g_s2[(10+ch)*NSLOT+slot], (double)q);
            }
        }
    }
    __threadfence();
    __syncthreads();
    if (tid==0) sLast = (atomicAdd(&g_cnt2, 1u) == NBL-1);
    __syncthreads();
    if (sLast){
        if (tid<20){
            double s=0.0;
            #pragma unroll
            for (int k=0;k<NSLOT;k++){
                s += __ldcg(&g_s2[tid*NSLOT+k]);
                g_s2[tid*NSLOT+k]=0.0;
            }
            sStat[tid]=s;
        }
        __syncthreads();
        if (tid<10){
            double m = sStat[tid]    * (1.0/(double)NP);
            double v = sStat[10+tid] * (1.0/(double)NP) - m*m;
            float a = g_r2[tid] * rsqrtf((float)v + 1e-5f);
            g_p2[tid]    = a;
            g_p2[10+tid] = be_r2[tid] - (float)(a*m);
        }
        if (tid==0) g_cnt2 = 0u;
    }
}

// ===== Pass C: node1 = ConvGRU(x=relu(bn2(y2)), h=f1) =====
__global__ void __launch_bounds__(NTH) k_passC(
    const float* __restrict__ f1,
    const float* __restrict__ Wg1, const float* __restrict__ bg1, const float* __restrict__ Wc1,
    float* __restrict__ node1)
{
    __shared__ float sWg[40], sWc[200], sP[20], sbg[2];
    int tid = threadIdx.x;
    for (int i=tid;i<40;i+=NTH)  sWg[i]=Wg1[i];
    for (int i=tid;i<200;i+=NTH) sWc[i]=Wc1[i];
    if (tid<20) sP[tid]=g_p2[tid];
    if (tid==0){ sbg[0]=bg1[0]; sbg[1]=bg1[1]; }
    __syncthreads();

    int idx = blockIdx.x*NTH + tid;
    int b = idx >> 14, p = idx & (HW-1);
    int base = b*Cn*HW + p;

    float cf[Cn], fv[Cn];
    #pragma unroll
    for (int o=0;o<Cn;o++){
        float yv = g_y2[base + o*HW];
        cf[o] = fmaxf(fmaf(sP[o], yv, sP[10+o]), 0.f);
        fv[o] = f1[base + o*HW];
    }
    float g0=sbg[0], g1=sbg[1];
    #pragma unroll
    for (int c=0;c<Cn;c++){
        g0 = fmaf(sWg[c],    cf[c], fmaf(sWg[10+c], fv[c], g0));
        g1 = fmaf(sWg[20+c], cf[c], fmaf(sWg[30+c], fv[c], g1));
    }
    float r = sigm(g0), u = sigm(g1);
    #pragma unroll
    for (int o=0;o<Cn;o++){
        float a=0.f;
        #pragma unroll
        for (int c=0;c<Cn;c++)
            a = fmaf(sWc[o*20+c], cf[c], fmaf(sWc[o*20+10+c], r*fv[c], a));
        node1[base+o*HW] = (1.f-u)*fv[o] + u*ftanh(a);
    }
}

extern "C" void kernel_launch(void* const* d_in, const int* in_sizes, int n_in,
                              void* d_out, int out_size)
{
    const float* f0    = (const float*)d_in[0];
    const float* f1    = (const float*)d_in[1];
    const float* h0    = (const float*)d_in[2];
    const float* h1    = (const float*)d_in[3];
    const float* h2    = (const float*)d_in[4];
    const float* W_att = (const float*)d_in[5];
    const float* b_att = (const float*)d_in[6];
    const float* W_r1  = (const float*)d_in[7];
    const float* g_r1  = (const float*)d_in[8];
    const float* be_r1 = (const float*)d_in[9];
    const float* W_r2  = (const float*)d_in[10];
    const float* g_r2  = (const float*)d_in[11];
    const float* be_r2 = (const float*)d_in[12];
    const float* Wg0   = (const float*)d_in[13];
    const float* bg0   = (const float*)d_in[14];
    const float* Wc0   = (const float*)d_in[15];
    const float* Wg1   = (const float*)d_in[16];
    const float* bg1   = (const float*)d_in[17];
    const float* Wc1   = (const float*)d_in[18];

    float* out   = (float*)d_out;
    float* node0 = out;                      // [8,10,128,128]
    float* node1 = out + Bn*Cn*HW;           // [8,10,128,128]
    float* att   = out + 2*Bn*Cn*HW;         // [8,1,128,128]

    k_passA<<<2*NBL, NTH>>>(f0, h0, f1, h1, h2, W_att, b_att,
                            W_r1, g_r1, be_r1, Wg0, bg0, Wc0, node0, att);
    k_passB<<<NBL, NTH>>>(W_r2, g_r2, be_r2);
    k_passC<<<NBL, NTH>>>(f1, Wg1, bg1, Wc1, node1);
}